// round 6
// baseline (speedup 1.0000x reference)
#include <cuda_runtime.h>

// Grouped shifted conv1d:
//   t = roll(x, +1, axis=3); patches = unfold(t, k=3, pad=1) along last axis
//   y[o,k,n,m] = sum_{i,j} patches[o*64+i, n, j, m] * W[i,k,j]
//   out = roll(y, +1, axis=2)  (H roll folded into store index)
//
// Grid: (56 rows, 2 groups). Block: 896 = 56 m x 4 kq x 4 iq.
// xs transposed to [u][i] (i contiguous) -> float4 x-tap loads.
// ws laid out [k][j][i] -> float4 W loads, warp-uniform (broadcast).

#define NT 896
#define XPITCH 68   // row stride in floats: 16B-aligned, limits bank conflicts

__global__ void __launch_bounds__(NT)
shiftconv_kernel(const float* __restrict__ x,
                 const float* __restrict__ W,
                 float* __restrict__ out)
{
    const int n = blockIdx.x;   // input H row 0..55
    const int o = blockIdx.y;   // channel group 0..1

    __shared__ float  xs[58 * XPITCH];   // xs[u][i]: rolled + padded, i contiguous
    __shared__ float  ws[16 * 3 * 64];   // ws[k][j][i]
    __shared__ float4 red[3 * 224];      // partials from i-quarters 1..3

    const int tid = threadIdx.x;
    const int m   = tid % 56;
    const int r   = tid / 56;       // 0..15
    const int kq  = r & 3;          // 0..3
    const int iq  = r >> 2;         // 0..3

    // zero pad rows u=0 and u=57
    if (tid < 128)
        xs[((tid & 1) ? 57 : 0) * XPITCH + (tid >> 1)] = 0.0f;

    // --- x LDGs first (longest latency), MLP=4; fused +1 circular roll ---
    const float* xg  = x + (o * 64) * 3136 + n * 56;
    const int    src = (m + 55) % 56;
    const float v0 = xg[(r     ) * 3136 + src];
    const float v1 = xg[(r + 16) * 3136 + src];
    const float v2 = xg[(r + 32) * 3136 + src];
    const float v3 = xg[(r + 48) * 3136 + src];

    // --- W staging overlapped with x loads in flight ---
    // src (i,k,j) row-major -> dst ws[k*192 + j*64 + i]
    #pragma unroll
    for (int s = 0; s < 4; ++s) {
        const int t = tid + s * NT;
        if (t < 3072) {
            const int i = t & 63;
            const int j = (t >> 6) % 3;
            const int k = t / 192;
            ws[t] = W[i * 48 + k * 3 + j];
        }
    }

    // transposed stores: row u = m+1, columns i
    {
        float* xr = xs + (m + 1) * XPITCH;
        xr[r     ] = v0;
        xr[r + 16] = v1;
        xr[r + 32] = v2;
        xr[r + 48] = v3;
    }
    __syncthreads();

    // --- compute: thread owns (m, kq, iq); i in 4 chunks of 4 ---
    const int kbase = kq * 4;
    float acc0 = 0.f, acc1 = 0.f, acc2 = 0.f, acc3 = 0.f;

    const float* x0 = xs + (m    ) * XPITCH + iq * 16;   // tap j=0 row
    const float* x1 = xs + (m + 1) * XPITCH + iq * 16;   // tap j=1 row
    const float* x2 = xs + (m + 2) * XPITCH + iq * 16;   // tap j=2 row
    const float* wb = ws + kbase * 192 + iq * 16;        // ws[kbase][0][iq*16]

    #pragma unroll
    for (int c = 0; c < 4; ++c) {
        const int ib = c * 4;
        const float4 xa = *reinterpret_cast<const float4*>(x0 + ib);
        const float4 xb = *reinterpret_cast<const float4*>(x1 + ib);
        const float4 xc = *reinterpret_cast<const float4*>(x2 + ib);

        #pragma unroll
        for (int kk = 0; kk < 4; ++kk) {
            const float* wk = wb + kk * 192 + ib;
            const float4 wj0 = *reinterpret_cast<const float4*>(wk);         // j=0
            const float4 wj1 = *reinterpret_cast<const float4*>(wk + 64);    // j=1
            const float4 wj2 = *reinterpret_cast<const float4*>(wk + 128);   // j=2

            float s;
            s  = xa.x * wj0.x + xb.x * wj1.x + xc.x * wj2.x;
            s += xa.y * wj0.y + xb.y * wj1.y + xc.y * wj2.y;
            s += xa.z * wj0.z + xb.z * wj1.z + xc.z * wj2.z;
            s += xa.w * wj0.w + xb.w * wj1.w + xc.w * wj2.w;

            if      (kk == 0) acc0 += s;
            else if (kk == 1) acc1 += s;
            else if (kk == 2) acc2 += s;
            else              acc3 += s;
        }
    }

    // --- 4-way partial reduction through smem ---
    const int part = kq * 56 + m;           // 0..223
    if (iq != 0)
        red[(iq - 1) * 224 + part] = make_float4(acc0, acc1, acc2, acc3);
    __syncthreads();

    if (iq == 0) {
        const float4 p0 = red[part];
        const float4 p1 = red[224 + part];
        const float4 p2 = red[448 + part];
        acc0 += p0.x + p1.x + p2.x;
        acc1 += p0.y + p1.y + p2.y;
        acc2 += p0.z + p1.z + p2.z;
        acc3 += p0.w + p1.w + p2.w;

        // store with the output H-roll folded in: y_out[n+1] = y[n]
        const int n_out = (n + 1) % 56;
        float* og = out + ((o * 16 + kbase) * 56 + n_out) * 56 + m;
        og[0 * 3136] = acc0;
        og[1 * 3136] = acc1;
        og[2 * 3136] = acc2;
        og[3 * 3136] = acc3;
    }
}

extern "C" void kernel_launch(void* const* d_in, const int* in_sizes, int n_in,
                              void* d_out, int out_size)
{
    const float* x = (const float*)d_in[0];   // (1,128,56,56) fp32
    const float* W = (const float*)d_in[1];   // (64,16,3) fp32
    float* out     = (float*)d_out;           // (1,32,56,56) fp32

    dim3 grid(56, 2);
    shiftconv_kernel<<<grid, NT>>>(x, W, out);
}

// round 9
// speedup vs baseline: 1.0791x; 1.0791x over previous
#include <cuda_runtime.h>

// Grouped shifted conv1d:
//   t = roll(x, +1, axis=3); patches = unfold(t, k=3, pad=1) along last axis
//   y[o,k,n,m] = sum_{i,j} patches[o*64+i, n, j, m] * W[i,k,j]
//   out = roll(y, +1, axis=2)  (H roll folded into store index)
//
// Grid: (56 rows, 2 groups). Block: 448 = 14 mq x 4 kq x 8 iq.
// Each thread computes a 4m x 4k register tile over 8 input channels:
// 6 x-taps serve 4 outputs (reuse), 48 independent FMAs per channel.

#define NT 448
#define XPITCH 60   // floats; i*60 is 16B-aligned so float4 row loads work

union Smem {
    struct {
        float xs[64 * XPITCH];   // xs[i][u]: rolled + zero-padded, u in [0,58)
        float ws[3 * 64 * 16];   // ws[j][i][k]: k contiguous -> float4 over k
    } s;
    float red[8 * 16 * 56];      // partials red[iq][k][m], reused after compute
};

__global__ void __launch_bounds__(NT)
shiftconv_kernel(const float* __restrict__ x,
                 const float* __restrict__ W,
                 float* __restrict__ out)
{
    __shared__ Smem sm;

    const int n = blockIdx.x;   // input H row 0..55
    const int o = blockIdx.y;   // channel group 0..1

    const int tid = threadIdx.x;
    const int mq  = tid % 14;          // 4-wide m tile index
    const int kq  = (tid / 14) % 4;    // 4-wide k tile index
    const int iq  = tid / 56;          // 0..7, 8-channel slice

    // zero pad columns u=0 and u=57
    if (tid < 128)
        sm.s.xs[(tid >> 1) * XPITCH + (tid & 1) * 57] = 0.0f;

    // --- stage x: 8 LDGs in flight per thread (448*8 = 64*56), fused roll ---
    // d = tid + s*448; 448 = 8*56 so u is constant per thread, i steps by 8.
    {
        const float* xg  = x + (o * 64) * 3136 + n * 56;
        const int    u   = tid % 56 + 1;          // 1..56
        const int    src = (tid % 56 + 55) % 56;  // (u-2) mod 56
        const int    i0  = tid / 56;              // 0..7
        #pragma unroll
        for (int s = 0; s < 8; ++s) {
            const int i = i0 + 8 * s;
            sm.s.xs[i * XPITCH + u] = xg[i * 3136 + src];
        }
    }

    // --- stage W: src (i,k,j) row-major -> ws[j*1024 + i*16 + k] ---
    #pragma unroll
    for (int s = 0; s < 7; ++s) {
        const int t = tid + s * NT;
        if (t < 3072) {
            const int k = t & 15;
            const int i = (t >> 4) & 63;
            const int j = t >> 10;
            sm.s.ws[t] = W[i * 48 + k * 3 + j];
        }
    }
    __syncthreads();

    // --- compute: 4m x 4k register tile, i in [iq*8, iq*8+8) ---
    const int mbase = mq * 4;
    const int kbase = kq * 4;
    float acc[4][4];                       // [kk][d]
    #pragma unroll
    for (int a = 0; a < 4; ++a)
        #pragma unroll
        for (int b = 0; b < 4; ++b) acc[a][b] = 0.f;

    const float* xrow = sm.s.xs + iq * 8 * XPITCH + mbase;
    const float* wrow = sm.s.ws + iq * 8 * 16 + kbase;

    #pragma unroll
    for (int ii = 0; ii < 8; ++ii) {
        // 6 x taps serve outputs mbase..mbase+3 (taps m..m+5 in padded coords)
        const float4 xlo = *reinterpret_cast<const float4*>(xrow + ii * XPITCH);
        const float2 xhi = *reinterpret_cast<const float2*>(xrow + ii * XPITCH + 4);
        const float xv[6] = { xlo.x, xlo.y, xlo.z, xlo.w, xhi.x, xhi.y };

        const float4 w0 = *reinterpret_cast<const float4*>(wrow + ii * 16);            // j=0, k vec
        const float4 w1 = *reinterpret_cast<const float4*>(wrow + ii * 16 + 1024);     // j=1
        const float4 w2 = *reinterpret_cast<const float4*>(wrow + ii * 16 + 2048);     // j=2
        const float wj[3][4] = { {w0.x,w0.y,w0.z,w0.w},
                                 {w1.x,w1.y,w1.z,w1.w},
                                 {w2.x,w2.y,w2.z,w2.w} };

        #pragma unroll
        for (int kk = 0; kk < 4; ++kk)
            #pragma unroll
            for (int d = 0; d < 4; ++d)
                acc[kk][d] += xv[d] * wj[0][kk]
                            + xv[d + 1] * wj[1][kk]
                            + xv[d + 2] * wj[2][kk];
    }

    // all xs/ws reads done before red aliases the same smem
    __syncthreads();

    // --- store partials: red[(iq*16 + k)*56 + m], float4 over d ---
    #pragma unroll
    for (int kk = 0; kk < 4; ++kk)
        *reinterpret_cast<float4*>(
            sm.red + (iq * 16 + kbase + kk) * 56 + mbase) =
            make_float4(acc[kk][0], acc[kk][1], acc[kk][2], acc[kk][3]);
    __syncthreads();

    // --- reduce 8 partials, store with output H-roll folded in ---
    // thread t: k = t/28, m-pair = t%28 -> outputs (k, 2mp), (k, 2mp+1)
    {
        const int k  = tid / 28;
        const int mp = (tid % 28) * 2;
        float2 srt = make_float2(0.f, 0.f);
        #pragma unroll
        for (int q = 0; q < 8; ++q) {
            const float2 p = *reinterpret_cast<const float2*>(
                sm.red + (q * 16 + k) * 56 + mp);
            srt.x += p.x;
            srt.y += p.y;
        }
        const int n_out = (n + 1) % 56;
        *reinterpret_cast<float2*>(
            out + ((o * 16 + k) * 56 + n_out) * 56 + mp) = srt;
    }
}

extern "C" void kernel_launch(void* const* d_in, const int* in_sizes, int n_in,
                              void* d_out, int out_size)
{
    const float* x = (const float*)d_in[0];   // (1,128,56,56) fp32
    const float* W = (const float*)d_in[1];   // (64,16,3) fp32
    float* out     = (float*)d_out;           // (1,32,56,56) fp32

    dim3 grid(56, 2);
    shiftconv_kernel<<<grid, NT>>>(x, W, out);
}

// round 10
// speedup vs baseline: 1.1583x; 1.0734x over previous
#include <cuda_runtime.h>

// Grouped shifted conv1d:
//   t = roll(x, +1, axis=3); patches = unfold(t, k=3, pad=1) along last axis
//   y[o,k,n,m] = sum_{i,j} patches[o*64+i, n, j, m] * W[i,k,j]
//   out = roll(y, +1, axis=2)  (H roll folded into store index)
//
// Grid: (56 rows, 2 groups). Block: 896 = 14 mq x 4 kq x 16 iq.
// Each thread: 4m x 4k register tile over 4 input channels (48 FMA/channel).
// Two-stage smem reduction: slices 8..15 RMW-merge into slabs 0..7, then
// 896 threads (= 16 k x 56 m) finish the 8-way sum with one store each.

#define NT 896
#define XPITCH 60   // floats; i*60 is 16B-aligned so float4 row loads work

union Smem {
    struct {
        float xs[64 * XPITCH];   // xs[i][u]: rolled + zero-padded, u in [0,58)
        float ws[3 * 64 * 16];   // ws[j][i][k]: k contiguous -> float4 over k
    } s;
    float red[8 * 16 * 56];      // partials red[slab][k][m], aliases after compute
};

__global__ void __launch_bounds__(NT)
shiftconv_kernel(const float* __restrict__ x,
                 const float* __restrict__ W,
                 float* __restrict__ out)
{
    __shared__ Smem sm;

    const int n = blockIdx.x;   // input H row 0..55
    const int o = blockIdx.y;   // channel group 0..1

    const int tid = threadIdx.x;
    const int mq  = tid % 14;          // 4-wide m tile index
    const int kq  = (tid / 14) % 4;    // 4-wide k tile index
    const int iq  = tid / 56;          // 0..15, 4-channel slice

    // zero pad columns u=0 and u=57
    if (tid < 128)
        sm.s.xs[(tid >> 1) * XPITCH + (tid & 1) * 57] = 0.0f;

    // --- stage x: 4 LDGs in flight per thread (896*4 = 64*56), fused roll ---
    // 896 = 16*56: u constant per thread, i steps by 16 -> coalesced over m.
    {
        const float* xg  = x + (o * 64) * 3136 + n * 56;
        const int    u   = tid % 56 + 1;          // 1..56
        const int    src = (tid % 56 + 55) % 56;  // (u-2) mod 56
        const int    i0  = tid / 56;              // 0..15
        #pragma unroll
        for (int s = 0; s < 4; ++s) {
            const int i = i0 + 16 * s;
            sm.s.xs[i * XPITCH + u] = xg[i * 3136 + src];
        }
    }

    // --- stage W: src (i,k,j) row-major -> ws[j*1024 + i*16 + k] ---
    #pragma unroll
    for (int s = 0; s < 4; ++s) {
        const int t = tid + s * NT;
        if (t < 3072) {
            const int k = t & 15;
            const int i = (t >> 4) & 63;
            const int j = t >> 10;
            sm.s.ws[t] = W[i * 48 + k * 3 + j];
        }
    }
    __syncthreads();

    // --- compute: 4m x 4k register tile, i in [iq*4, iq*4+4) ---
    const int mbase = mq * 4;
    const int kbase = kq * 4;
    float acc[4][4];                       // [kk][d]
    #pragma unroll
    for (int a = 0; a < 4; ++a)
        #pragma unroll
        for (int b = 0; b < 4; ++b) acc[a][b] = 0.f;

    const float* xrow = sm.s.xs + iq * 4 * XPITCH + mbase;
    const float* wrow = sm.s.ws + iq * 4 * 16 + kbase;

    #pragma unroll
    for (int ii = 0; ii < 4; ++ii) {
        // 6 x taps serve outputs mbase..mbase+3 (taps m..m+5 in padded coords)
        const float4 xlo = *reinterpret_cast<const float4*>(xrow + ii * XPITCH);
        const float2 xhi = *reinterpret_cast<const float2*>(xrow + ii * XPITCH + 4);
        const float xv[6] = { xlo.x, xlo.y, xlo.z, xlo.w, xhi.x, xhi.y };

        const float4 w0 = *reinterpret_cast<const float4*>(wrow + ii * 16);            // j=0
        const float4 w1 = *reinterpret_cast<const float4*>(wrow + ii * 16 + 1024);     // j=1
        const float4 w2 = *reinterpret_cast<const float4*>(wrow + ii * 16 + 2048);     // j=2
        const float wj[3][4] = { {w0.x,w0.y,w0.z,w0.w},
                                 {w1.x,w1.y,w1.z,w1.w},
                                 {w2.x,w2.y,w2.z,w2.w} };

        #pragma unroll
        for (int kk = 0; kk < 4; ++kk)
            #pragma unroll
            for (int d = 0; d < 4; ++d)
                acc[kk][d] += xv[d] * wj[0][kk]
                            + xv[d + 1] * wj[1][kk]
                            + xv[d + 2] * wj[2][kk];
    }

    // all xs/ws reads done before red aliases the same smem
    __syncthreads();

    // --- stage A: slices 0..7 write their slab ---
    if (iq < 8) {
        #pragma unroll
        for (int kk = 0; kk < 4; ++kk)
            *reinterpret_cast<float4*>(
                sm.red + (iq * 16 + kbase + kk) * 56 + mbase) =
                make_float4(acc[kk][0], acc[kk][1], acc[kk][2], acc[kk][3]);
    }
    __syncthreads();

    // --- stage B: slices 8..15 merge into slab (iq-8); single writer per slot ---
    if (iq >= 8) {
        const int q = iq - 8;
        #pragma unroll
        for (int kk = 0; kk < 4; ++kk) {
            float4* p = reinterpret_cast<float4*>(
                sm.red + (q * 16 + kbase + kk) * 56 + mbase);
            float4 v = *p;
            v.x += acc[kk][0];
            v.y += acc[kk][1];
            v.z += acc[kk][2];
            v.w += acc[kk][3];
            *p = v;
        }
    }
    __syncthreads();

    // --- final: 896 threads = 16 k x 56 m; 8-way sum + rolled store ---
    {
        const int k = tid / 56;
        const int m = tid % 56;
        float s = 0.f;
        #pragma unroll
        for (int q = 0; q < 8; ++q)
            s += sm.red[(q * 16 + k) * 56 + m];
        const int n_out = (n + 1) % 56;
        out[((o * 16 + k) * 56 + n_out) * 56 + m] = s;
    }
}

extern "C" void kernel_launch(void* const* d_in, const int* in_sizes, int n_in,
                              void* d_out, int out_size)
{
    const float* x = (const float*)d_in[0];   // (1,128,56,56) fp32
    const float* W = (const float*)d_in[1];   // (64,16,3) fp32
    float* out     = (float*)d_out;           // (1,32,56,56) fp32

    dim3 grid(56, 2);
    shiftconv_kernel<<<grid, NT>>>(x, W, out);
}